// round 5
// baseline (speedup 1.0000x reference)
#include <cuda_runtime.h>

// ---------------- problem constants (fixed shapes) ----------------
#define BB   4
#define CC   64
#define HH   288
#define WW   432
#define PW   72            // W / TEM
#define TEM_ 6
#define VV   (HH*WW)       // 124416
#define RN   ((HH-1)*PW)   // 20664  vertical edges per phase
#define CN   (HH*(PW-1))   // 20448  horizontal edges per phase
#define XN   (HH*PW)       // 20736  cross edges per phase pair
#define PB   (RN+CN)       // 41112  weight-layout per-phase block
#define EE   (6*RN+6*CN+5*XN) // 350352 total edges
#define NOUT (VV-1)        // 124415 output entries per batch
#define SENT 0xFFFFFFFFFFFFFFFFULL
#define NROUNDS 18

typedef unsigned long long u64;

// ---------------- scratch (device globals; no allocation) ----------------
__device__ u64 g_keys[BB*EE];          // (w_bits<<32)|e at weight-layout position e
__device__ u64 g_minkey[BB*VV];        // per-component min key
__device__ u64 g_euv[BB*EE];           // current (cu,cv) of surviving edge e
__device__ int g_comp[BB*VV];          // root-domain component map
__device__ int g_parent[BB*VV];
__device__ unsigned char g_mask[BB*EE];
__device__ ulonglong2 g_elist[2][BB*EE];  // {key, (cv<<32)|cu}
__device__ int g_ecnt[2][BB];
__device__ int g_roots[2][BB*VV];
__device__ int g_rcnt[2][BB];

// endpoints of edge e in INDEX layout: [rows x6 | cols x6 | cross x5]
__device__ __forceinline__ void edge_uv(int e, int& u, int& v) {
    if (e < 6*RN) {
        int i = e / RN; int j = e - i*RN;
        int r = j / PW;  int c = j - r*PW;
        u = r*WW + i*PW + c; v = u + WW;
    } else if (e < 6*RN + 6*CN) {
        int t = e - 6*RN;
        int i = t / CN; int j = t - i*CN;
        int r = j / (PW-1); int c = j - r*(PW-1);
        u = r*WW + i*PW + c; v = u + 1;
    } else {
        int t = e - 6*RN - 6*CN;
        int i = t / XN; int j = t - i*XN;
        int r = j / PW; int c = j - r*PW;
        u = r*WW + i*PW + c; v = u + PW;
    }
}

__device__ __forceinline__ int chase_root(const int* par, int c) {
    while (true) {
        int p = par[c];
        if (p == c) break;
        int gp = par[p];
        if (gp == c) { c = (c < p) ? c : p; break; }  // 2-cycle: min of pair
        c = p;
    }
    return c;
}

// ---------------- init ----------------
__global__ void init_kernel() {
    int idx = blockIdx.x * blockDim.x + threadIdx.x;
    if (idx < BB*VV) g_minkey[idx] = SENT;
    if (idx < BB*EE) g_mask[idx] = 0;
    if (idx < BB) {
        g_ecnt[0][idx] = 0; g_ecnt[1][idx] = 0;
        g_rcnt[0][idx] = 0; g_rcnt[1][idx] = 0;
    }
}

// ---------------- weights: thread-per-pixel (down / right / cross-right) ----
__global__ void weight_kernel(const float* __restrict__ fm) {
    int idx = blockIdx.x * blockDim.x + threadIdx.x;
    if (idx >= BB*VV) return;
    int b   = idx / VV;
    int pix = idx - b*VV;
    int r   = pix / WW;
    int col = pix - r*WW;
    int ph  = col / PW;
    int c   = col - ph*PW;

    bool hasV = (r  < HH-1);
    bool hasH = (c  < PW-1);
    bool hasX = (ph < TEM_-1);

    const float* base = fm + (size_t)b * CC * VV + pix;
    float sv = 0.f, sh = 0.f, sx = 0.f;
    #pragma unroll 8
    for (int ch = 0; ch < CC; ch++) {
        const float* p = base + (size_t)ch * VV;
        float x0 = __ldg(p);
        if (hasV) { float d = x0 - __ldg(p + WW); sv += d*d; }
        if (hasH) { float d = x0 - __ldg(p + 1);  sh += d*d; }
        if (hasX) { float d = x0 - __ldg(p + PW); sx += d*d; }
    }
    u64* kb = g_keys + (size_t)b * EE;
    if (hasV) {
        int e = ph*PB + r*PW + c;
        kb[e] = ((u64)__float_as_uint(sv) << 32) | (unsigned)e;
    }
    if (hasH) {
        int e = ph*PB + RN + r*(PW-1) + c;
        kb[e] = ((u64)__float_as_uint(sh) << 32) | (unsigned)e;
    }
    if (hasX) {
        int e = 6*PB + ph*XN + r*PW + c;
        kb[e] = ((u64)__float_as_uint(sx) << 32) | (unsigned)e;
    }
}

// ---------------- round 0 (comp = identity) ----------------
__global__ void edge0_kernel() {
    int e = blockIdx.x * blockDim.x + threadIdx.x;
    if (e >= EE) return;
    int b = blockIdx.y;
    int u, v; edge_uv(e, u, v);
    u64 k = g_keys[(size_t)b*EE + e];
    atomicMin(&g_minkey[b*VV + u], k);
    atomicMin(&g_minkey[b*VV + v], k);
}

__global__ void select0_kernel() {
    int c = blockIdx.x * blockDim.x + threadIdx.x;
    if (c >= VV) return;
    int b = blockIdx.y;
    u64 mk = g_minkey[b*VV + c];
    int par = c;
    if (mk != SENT) {
        g_minkey[b*VV + c] = SENT;
        int e = (int)(unsigned)(mk & 0xFFFFFFFFu);
        g_mask[b*EE + e] = 1;
        int u, v; edge_uv(e, u, v);
        par = (u == c) ? v : u;
    }
    g_parent[b*VV + c] = par;
}

__global__ void chase0_kernel() {
    int vtx = blockIdx.x * blockDim.x + threadIdx.x;
    if (vtx >= VV) return;
    int b = blockIdx.y;
    int c = chase_root(g_parent + b*VV, vtx);
    g_comp[b*VV + vtx] = c;
    if (c == vtx) {
        int pos = atomicAdd(&g_rcnt[0][b], 1);
        g_roots[0][b*VV + pos] = vtx;
    }
}

// ---------------- round 1 (implicit edges, comp over V; appends -> list 0) ----
__global__ void edge1_kernel() {
    int e = blockIdx.x * blockDim.x + threadIdx.x;
    if (e >= EE) return;
    int b = blockIdx.y;
    int u, v; edge_uv(e, u, v);
    int cu = g_comp[b*VV + u];
    int cv = g_comp[b*VV + v];
    if (cu == cv) return;
    u64 k = g_keys[(size_t)b*EE + e];
    atomicMin(&g_minkey[b*VV + cu], k);
    atomicMin(&g_minkey[b*VV + cv], k);
    u64 uv = ((u64)(unsigned)cv << 32) | (unsigned)cu;
    g_euv[(size_t)b*EE + e] = uv;
    int pos = atomicAdd(&g_ecnt[0][b], 1);
    g_elist[0][(size_t)b*EE + pos] = make_ulonglong2(k, uv);
}

// select over root list RB, reset rcnt[RST]
template<int RB, int RST>
__global__ void select_roots_kernel() {
    int b = blockIdx.y;
    if (blockIdx.x == 0 && threadIdx.x == 0) g_rcnt[RST][b] = 0;
    int n = g_rcnt[RB][b];
    for (int i = blockIdx.x * blockDim.x + threadIdx.x; i < n; i += gridDim.x * blockDim.x) {
        int c = g_roots[RB][b*VV + i];
        u64 mk = g_minkey[b*VV + c];
        int par = c;
        if (mk != SENT) {
            g_minkey[b*VV + c] = SENT;
            int e = (int)(unsigned)(mk & 0xFFFFFFFFu);
            g_mask[b*EE + e] = 1;
            u64 uv = g_euv[(size_t)b*EE + e];
            int cu = (int)(unsigned)(uv & 0xFFFFFFFFu);
            int cv = (int)(unsigned)(uv >> 32);
            par = (cu == c) ? cv : cu;
        }
        g_parent[b*VV + c] = par;
    }
}

// chase over root list RB, append new roots -> list WB
template<int RB, int WB>
__global__ void chase_roots_kernel() {
    int b = blockIdx.y;
    int n = g_rcnt[RB][b];
    for (int i = blockIdx.x * blockDim.x + threadIdx.x; i < n; i += gridDim.x * blockDim.x) {
        int x = g_roots[RB][b*VV + i];
        int c = chase_root(g_parent + b*VV, x);
        g_comp[b*VV + x] = c;
        if (c == x) {
            int pos = atomicAdd(&g_rcnt[WB][b], 1);
            g_roots[WB][b*VV + pos] = x;
        }
    }
}

// ---------------- round 2 (explicit list 0 -> list 1) ----------------
__global__ void edge2_kernel() {
    int b = blockIdx.y;
    int n = g_ecnt[0][b];
    for (int i = blockIdx.x * blockDim.x + threadIdx.x; i < n; i += gridDim.x * blockDim.x) {
        ulonglong2 ed = g_elist[0][(size_t)b*EE + i];
        int u = (int)(unsigned)(ed.y & 0xFFFFFFFFu);
        int v = (int)(unsigned)(ed.y >> 32);
        int cu = g_comp[b*VV + u];
        int cv = g_comp[b*VV + v];
        if (cu == cv) continue;
        atomicMin(&g_minkey[b*VV + cu], ed.x);
        atomicMin(&g_minkey[b*VV + cv], ed.x);
        int e = (int)(unsigned)(ed.x & 0xFFFFFFFFu);
        u64 uv = ((u64)(unsigned)cv << 32) | (unsigned)cu;
        g_euv[(size_t)b*EE + e] = uv;
        int pos = atomicAdd(&g_ecnt[1][b], 1);
        g_elist[1][(size_t)b*EE + pos] = make_ulonglong2(ed.x, uv);
    }
}

// ---------------- finisher: rounds 3..17 in one launch (1 block / batch) ----
__global__ void __launch_bounds__(1024, 1) finisher_kernel() {
    int b = blockIdx.x;
    int tid = threadIdx.x;
    __shared__ int s_ecur, s_enxt, s_rcur, s_rnxt;
    if (tid == 0) { s_ecur = g_ecnt[1][b]; s_rcur = g_rcnt[0][b]; }
    __syncthreads();

    int ebuf = 1, rbuf = 0;
    u64* minkey = g_minkey + b*VV;
    int* parent = g_parent + b*VV;
    int* comp   = g_comp + b*VV;
    u64* euv    = g_euv + (size_t)b*EE;
    unsigned char* mask = g_mask + (size_t)b*EE;

    for (int r = 3; r < NROUNDS; r++) {
        if (s_ecur == 0) break;
        if (tid == 0) { s_enxt = 0; s_rnxt = 0; }
        __syncthreads();

        // edge phase
        int ecur = s_ecur;
        for (int i = tid; i < ecur; i += 1024) {
            ulonglong2 ed = g_elist[ebuf][(size_t)b*EE + i];
            int u = (int)(unsigned)(ed.y & 0xFFFFFFFFu);
            int v = (int)(unsigned)(ed.y >> 32);
            int cu = comp[u];
            int cv = comp[v];
            if (cu == cv) continue;
            atomicMin(&minkey[cu], ed.x);
            atomicMin(&minkey[cv], ed.x);
            int e = (int)(unsigned)(ed.x & 0xFFFFFFFFu);
            u64 uv = ((u64)(unsigned)cv << 32) | (unsigned)cu;
            euv[e] = uv;
            int pos = atomicAdd(&s_enxt, 1);
            g_elist[ebuf^1][(size_t)b*EE + pos] = make_ulonglong2(ed.x, uv);
        }
        __syncthreads();

        // select phase
        int rcur = s_rcur;
        for (int i = tid; i < rcur; i += 1024) {
            int c = g_roots[rbuf][b*VV + i];
            u64 mk = minkey[c];
            int par = c;
            if (mk != SENT) {
                minkey[c] = SENT;
                int e = (int)(unsigned)(mk & 0xFFFFFFFFu);
                mask[e] = 1;
                u64 uv = euv[e];
                int cu = (int)(unsigned)(uv & 0xFFFFFFFFu);
                int cv = (int)(unsigned)(uv >> 32);
                par = (cu == c) ? cv : cu;
            }
            parent[c] = par;
        }
        __syncthreads();

        // chase phase
        for (int i = tid; i < rcur; i += 1024) {
            int x = g_roots[rbuf][b*VV + i];
            int c = chase_root(parent, x);
            comp[x] = c;
            if (c == x) {
                int pos = atomicAdd(&s_rnxt, 1);
                g_roots[rbuf^1][b*VV + pos] = x;
            }
        }
        __syncthreads();
        if (tid == 0) { s_ecur = s_enxt; s_rcur = s_rnxt; }
        ebuf ^= 1; rbuf ^= 1;
        __syncthreads();
    }
}

// ---------------- output (FLOAT32): prefill pad, then streaming compaction ----
__global__ void prefill_kernel(float* out, int total) {
    int i = blockIdx.x * blockDim.x + threadIdx.x;
    if (i < total) out[i] = (float)EE;
}

__global__ void compact_kernel(float* __restrict__ out, int stride) {
    int b    = blockIdx.x;
    int tid  = threadIdx.x;
    int lane = tid & 31;
    int w    = tid >> 5;

    __shared__ int wsum[32];
    __shared__ int s_base;
    __shared__ int s_total;
    if (tid == 0) s_base = 0;
    __syncthreads();

    const unsigned char* mb = g_mask + (size_t)b*EE;
    float* ob = out + (size_t)b*stride;

    for (int chunk = 0; chunk < EE; chunk += 4096) {
        int e0 = chunk + tid*4;
        int m0 = (e0 + 0 < EE) ? mb[e0 + 0] : 0;
        int m1 = (e0 + 1 < EE) ? mb[e0 + 1] : 0;
        int m2 = (e0 + 2 < EE) ? mb[e0 + 2] : 0;
        int m3 = (e0 + 3 < EE) ? mb[e0 + 3] : 0;
        int cnt = m0 + m1 + m2 + m3;

        int inc = cnt;
        #pragma unroll
        for (int off = 1; off < 32; off <<= 1) {
            int y = __shfl_up_sync(0xffffffffu, inc, off);
            if (lane >= off) inc += y;
        }
        if (lane == 31) wsum[w] = inc;
        __syncthreads();
        if (w == 0) {
            int v = wsum[lane];
            int iv = v;
            #pragma unroll
            for (int off = 1; off < 32; off <<= 1) {
                int y = __shfl_up_sync(0xffffffffu, iv, off);
                if (lane >= off) iv += y;
            }
            wsum[lane] = iv - v;
            if (lane == 31) s_total = iv;
        }
        __syncthreads();

        int base = s_base;
        int pos = base + wsum[w] + (inc - cnt);
        if (m0) { if (pos < stride) ob[pos] = (float)(e0 + 0); pos++; }
        if (m1) { if (pos < stride) ob[pos] = (float)(e0 + 1); pos++; }
        if (m2) { if (pos < stride) ob[pos] = (float)(e0 + 2); pos++; }
        if (m3) { if (pos < stride) ob[pos] = (float)(e0 + 3); pos++; }

        __syncthreads();
        if (tid == 0) s_base = base + s_total;
        __syncthreads();
    }
}

// ---------------- launch ----------------
extern "C" void kernel_launch(void* const* d_in, const int* in_sizes, int n_in,
                              void* d_out, int out_size) {
    const float* fm = (const float*)d_in[0];
    float* out = (float*)d_out;
    (void)in_sizes; (void)n_in;

    int stride = (out_size % BB == 0) ? (out_size / BB) : NOUT;

    const int T = 256;
    init_kernel<<<(BB*EE + T - 1) / T, T>>>();
    weight_kernel<<<(BB*VV + T - 1) / T, T>>>(fm);

    dim3 egrid((EE + T - 1) / T, BB);
    dim3 vgrid((VV + T - 1) / T, BB);
    dim3 rgrid(128, BB);   // grid-stride over root lists
    dim3 e2grid(512, BB);  // grid-stride over explicit edge list

    edge0_kernel  <<<egrid, T>>>();
    select0_kernel<<<vgrid, T>>>();
    chase0_kernel <<<vgrid, T>>>();

    edge1_kernel  <<<egrid, T>>>();
    select_roots_kernel<0,1><<<rgrid, T>>>();
    chase_roots_kernel <0,1><<<rgrid, T>>>();

    edge2_kernel  <<<e2grid, T>>>();
    select_roots_kernel<1,0><<<rgrid, T>>>();
    chase_roots_kernel <1,0><<<rgrid, T>>>();

    finisher_kernel<<<BB, 1024>>>();

    prefill_kernel<<<(out_size + T - 1) / T, T>>>(out, out_size);
    compact_kernel<<<BB, 1024>>>(out, stride);
}

// round 6
// speedup vs baseline: 3.3864x; 3.3864x over previous
#include <cuda_runtime.h>

// ---------------- problem constants (fixed shapes) ----------------
#define BB   4
#define CC   64
#define HH   288
#define WW   432
#define PW   72            // W / TEM
#define TEM_ 6
#define VV   (HH*WW)       // 124416
#define RN   ((HH-1)*PW)   // 20664  vertical edges per phase
#define CN   (HH*(PW-1))   // 20448  horizontal edges per phase
#define XN   (HH*PW)       // 20736  cross edges per phase pair
#define PB   (RN+CN)       // 41112  weight-layout per-phase block
#define EE   (6*RN+6*CN+5*XN) // 350352 total edges
#define NOUT (VV-1)        // 124415 output entries per batch
#define SENT 0xFFFFFFFFFFFFFFFFULL
#define NROUNDS 18

#define NBLK 32                    // blocks per batch (128 total <= 148 SMs -> co-resident)
#define TPB  (NBLK*1024)           // threads per batch
#define SEG  ((EE + NBLK - 1) / NBLK)  // compaction segment per block

typedef unsigned long long u64;

// ---------------- scratch (device globals; no allocation) ----------------
__device__ u64 g_keys[BB*EE];          // (w_bits<<32)|e at weight-layout position e
__device__ u64 g_minkey[BB*VV];        // per-component min key
__device__ u64 g_euv[BB*EE];           // current (cu,cv) of surviving edge e
__device__ int g_comp[BB*VV];
__device__ int g_parent[BB*VV];
__device__ unsigned char g_mask[BB*EE];
__device__ ulonglong2 g_elist[2][BB*EE];  // {key, (cv<<32)|cu}
__device__ int g_ecnt[NROUNDS][BB];
__device__ int g_rcnt[NROUNDS][BB];
__device__ int g_roots[2][BB*VV];
__device__ unsigned g_barcnt[BB];
__device__ int g_bcnt[BB*NBLK];

// endpoints of edge e in INDEX layout: [rows x6 | cols x6 | cross x5]
__device__ __forceinline__ void edge_uv(int e, int& u, int& v) {
    if (e < 6*RN) {
        int i = e / RN; int j = e - i*RN;
        int r = j / PW;  int c = j - r*PW;
        u = r*WW + i*PW + c; v = u + WW;
    } else if (e < 6*RN + 6*CN) {
        int t = e - 6*RN;
        int i = t / CN; int j = t - i*CN;
        int r = j / (PW-1); int c = j - r*(PW-1);
        u = r*WW + i*PW + c; v = u + 1;
    } else {
        int t = e - 6*RN - 6*CN;
        int i = t / XN; int j = t - i*XN;
        int r = j / PW; int c = j - r*PW;
        u = r*WW + i*PW + c; v = u + PW;
    }
}

__device__ __forceinline__ int chase_root(const int* par, int c) {
    while (true) {
        int p = par[c];
        if (p == c) break;
        int gp = par[p];
        if (gp == c) { c = (c < p) ? c : p; break; }  // 2-cycle: min of pair
        c = p;
    }
    return c;
}

// per-batch grid barrier (all NBLK blocks of batch b co-resident by construction)
__device__ __forceinline__ void batch_barrier(int b, unsigned& target) {
    __syncthreads();
    if (threadIdx.x == 0) {
        __threadfence();
        atomicAdd(&g_barcnt[b], 1u);
        target += NBLK;
        volatile unsigned* p = &g_barcnt[b];
        while (*p < target) { __nanosleep(64); }
        __threadfence();
    }
    __syncthreads();
}

// warp-aggregated list append; must be called by all 32 lanes
__device__ __forceinline__ int warp_reserve(int* ctr, bool pred) {
    unsigned ball = __ballot_sync(0xffffffffu, pred);
    int lane = threadIdx.x & 31;
    int total = __popc(ball);
    int base = 0;
    if (lane == 0 && total) base = atomicAdd(ctr, total);
    base = __shfl_sync(0xffffffffu, base, 0);
    return base + __popc(ball & ((1u << lane) - 1u));
}

// ---------------- init ----------------
__global__ void init_kernel() {
    int idx = blockIdx.x * blockDim.x + threadIdx.x;
    if (idx < BB*VV) g_minkey[idx] = SENT;
    if (idx < BB*EE) g_mask[idx] = 0;
    if (idx < NROUNDS*BB) {
        (&g_ecnt[0][0])[idx] = 0;
        (&g_rcnt[0][0])[idx] = 0;
    }
    if (idx < BB) g_barcnt[idx] = 0;
    if (idx < BB*NBLK) g_bcnt[idx] = 0;
}

// ---------------- weights: thread-per-pixel (down / right / cross-right) ----
__global__ void weight_kernel(const float* __restrict__ fm) {
    int idx = blockIdx.x * blockDim.x + threadIdx.x;
    if (idx >= BB*VV) return;
    int b   = idx / VV;
    int pix = idx - b*VV;
    int r   = pix / WW;
    int col = pix - r*WW;
    int ph  = col / PW;
    int c   = col - ph*PW;

    bool hasV = (r  < HH-1);
    bool hasH = (c  < PW-1);
    bool hasX = (ph < TEM_-1);

    const float* base = fm + (size_t)b * CC * VV + pix;
    float sv = 0.f, sh = 0.f, sx = 0.f;
    #pragma unroll 8
    for (int ch = 0; ch < CC; ch++) {
        const float* p = base + (size_t)ch * VV;
        float x0 = __ldg(p);
        if (hasV) { float d = x0 - __ldg(p + WW); sv += d*d; }
        if (hasH) { float d = x0 - __ldg(p + 1);  sh += d*d; }
        if (hasX) { float d = x0 - __ldg(p + PW); sx += d*d; }
    }
    u64* kb = g_keys + (size_t)b * EE;
    if (hasV) {
        int e = ph*PB + r*PW + c;
        kb[e] = ((u64)__float_as_uint(sv) << 32) | (unsigned)e;
    }
    if (hasH) {
        int e = ph*PB + RN + r*(PW-1) + c;
        kb[e] = ((u64)__float_as_uint(sh) << 32) | (unsigned)e;
    }
    if (hasX) {
        int e = 6*PB + ph*XN + r*PW + c;
        kb[e] = ((u64)__float_as_uint(sx) << 32) | (unsigned)e;
    }
}

// ---------------- persistent Boruvka + compaction ----------------
__global__ void __launch_bounds__(1024, 1) boruvka_kernel(float* __restrict__ out, int stride) {
    int b   = blockIdx.y;
    int tid = threadIdx.x;
    int gt  = blockIdx.x * 1024 + tid;
    unsigned bar_target = 0;

    u64* minkey = g_minkey + b*VV;
    u64* keys   = g_keys + (size_t)b*EE;
    u64* euv    = g_euv  + (size_t)b*EE;
    int* parent = g_parent + b*VV;
    int* comp   = g_comp + b*VV;
    unsigned char* mask = g_mask + (size_t)b*EE;

    // ===== round 0: edge phase (comp = identity) =====
    for (int e = gt; e < EE; e += TPB) {
        int u, v; edge_uv(e, u, v);
        u64 k = keys[e];
        atomicMin(&minkey[u], k);
        atomicMin(&minkey[v], k);
    }
    batch_barrier(b, bar_target);

    // round 0: select over all V
    for (int c = gt; c < VV; c += TPB) {
        u64 mk = minkey[c];
        int par = c;
        if (mk != SENT) {
            minkey[c] = SENT;
            int e = (int)(unsigned)(mk & 0xFFFFFFFFu);
            mask[e] = 1;
            int u, v; edge_uv(e, u, v);
            par = (u == c) ? v : u;
        }
        parent[c] = par;
    }
    batch_barrier(b, bar_target);

    // round 0: chase over all V, collect roots -> roots[0]
    {
        const int nn = ((VV + TPB - 1) / TPB) * TPB;
        for (int x = gt; x < nn; x += TPB) {
            bool isroot = false;
            int c = 0;
            if (x < VV) {
                c = chase_root(parent, x);
                comp[x] = c;
                isroot = (c == x);
            }
            int pos = warp_reserve(&g_rcnt[0][b], isroot);
            if (isroot) g_roots[0][b*VV + pos] = x;
        }
    }
    batch_barrier(b, bar_target);

    // ===== rounds 1..17 =====
    for (int r = 1; r < NROUNDS; r++) {
        int ebuf = r & 1;          // write buffer this round
        int rb   = (r - 1) & 1;    // root read buffer
        int wb   = r & 1;          // root write buffer

        // edge phase
        if (r == 1) {
            const int nn = ((EE + TPB - 1) / TPB) * TPB;
            for (int i = gt; i < nn; i += TPB) {
                bool pred = false; u64 k = 0, uvp = 0;
                if (i < EE) {
                    int u, v; edge_uv(i, u, v);
                    int cu = comp[u], cv = comp[v];
                    if (cu != cv) {
                        pred = true;
                        k = keys[i];
                        atomicMin(&minkey[cu], k);
                        atomicMin(&minkey[cv], k);
                        uvp = ((u64)(unsigned)cv << 32) | (unsigned)cu;
                        euv[i] = uvp;
                    }
                }
                int pos = warp_reserve(&g_ecnt[1][b], pred);
                if (pred) g_elist[ebuf][(size_t)b*EE + pos] = make_ulonglong2(k, uvp);
            }
        } else {
            int n = g_ecnt[r-1][b];
            const ulonglong2* src = g_elist[ebuf ^ 1] + (size_t)b*EE;
            ulonglong2* dst = g_elist[ebuf] + (size_t)b*EE;
            int nn = ((n + TPB - 1) / TPB) * TPB;
            for (int i = gt; i < nn; i += TPB) {
                bool pred = false; u64 k = 0, uvp = 0;
                if (i < n) {
                    ulonglong2 ed = src[i];
                    int u = (int)(unsigned)(ed.y & 0xFFFFFFFFu);
                    int v = (int)(unsigned)(ed.y >> 32);
                    int cu = comp[u], cv = comp[v];
                    if (cu != cv) {
                        pred = true;
                        k = ed.x;
                        atomicMin(&minkey[cu], k);
                        atomicMin(&minkey[cv], k);
                        uvp = ((u64)(unsigned)cv << 32) | (unsigned)cu;
                        euv[(unsigned)(k & 0xFFFFFFFFu)] = uvp;
                    }
                }
                int pos = warp_reserve(&g_ecnt[r][b], pred);
                if (pred) dst[pos] = make_ulonglong2(k, uvp);
            }
        }
        batch_barrier(b, bar_target);

        if (g_ecnt[r][b] == 0) break;   // nothing survived -> done

        // select phase over root list
        {
            int n = g_rcnt[r-1][b];
            const int* rl = g_roots[rb] + b*VV;
            for (int i = gt; i < n; i += TPB) {
                int c = rl[i];
                u64 mk = minkey[c];
                int par = c;
                if (mk != SENT) {
                    minkey[c] = SENT;
                    int e = (int)(unsigned)(mk & 0xFFFFFFFFu);
                    mask[e] = 1;
                    u64 uvp = euv[e];
                    int cu = (int)(unsigned)(uvp & 0xFFFFFFFFu);
                    int cv = (int)(unsigned)(uvp >> 32);
                    par = (cu == c) ? cv : cu;
                }
                parent[c] = par;
            }
        }
        batch_barrier(b, bar_target);

        // chase phase over root list, collect surviving roots
        {
            int n = g_rcnt[r-1][b];
            const int* rl = g_roots[rb] + b*VV;
            int nn = ((n + TPB - 1) / TPB) * TPB;
            for (int i = gt; i < nn; i += TPB) {
                bool isroot = false;
                int x = 0;
                if (i < n) {
                    x = rl[i];
                    int c = chase_root(parent, x);
                    comp[x] = c;
                    isroot = (c == x);
                }
                int pos = warp_reserve(&g_rcnt[r][b], isroot);
                if (isroot) g_roots[wb][b*VV + pos] = x;
            }
        }
        batch_barrier(b, bar_target);
    }

    // ===== fused compaction: mask -> ascending edge indices (float out) =====
    float* ob = out + (size_t)b * stride;

    // pass 1: count this block's segment
    {
        int s0 = blockIdx.x * SEG;
        int s1 = min(EE, s0 + SEG);
        int cnt = 0;
        for (int i = s0 + tid; i < s1; i += 1024) cnt += mask[i];
        __shared__ int s_red[32];
        int lane = tid & 31, wid = tid >> 5;
        #pragma unroll
        for (int off = 16; off > 0; off >>= 1) cnt += __shfl_down_sync(0xffffffffu, cnt, off);
        if (lane == 0) s_red[wid] = cnt;
        __syncthreads();
        if (wid == 0) {
            int v = s_red[lane];
            #pragma unroll
            for (int off = 16; off > 0; off >>= 1) v += __shfl_down_sync(0xffffffffu, v, off);
            if (lane == 0) g_bcnt[b*NBLK + blockIdx.x] = v;
        }
    }
    batch_barrier(b, bar_target);

    // block base = exclusive sum over preceding blocks
    __shared__ int s_base;
    if (tid < 32) {
        int v = g_bcnt[b*NBLK + tid];
        int iv = v;
        #pragma unroll
        for (int off = 1; off < 32; off <<= 1) {
            int y = __shfl_up_sync(0xffffffffu, iv, off);
            if (tid >= off) iv += y;
        }
        if (tid == (int)blockIdx.x) s_base = iv - v;
    }
    __syncthreads();

    // pass 2: ordered scatter within segment
    {
        int s0 = blockIdx.x * SEG;
        int s1 = min(EE, s0 + SEG);
        __shared__ int wsum[32];
        __shared__ int s_run, s_tot;
        if (tid == 0) s_run = s_base;
        __syncthreads();
        int lane = tid & 31, wid = tid >> 5;
        for (int chunk = s0; chunk < s1; chunk += 4096) {
            int e0 = chunk + tid*4;
            int m0 = (e0 + 0 < s1) ? mask[e0 + 0] : 0;
            int m1 = (e0 + 1 < s1) ? mask[e0 + 1] : 0;
            int m2 = (e0 + 2 < s1) ? mask[e0 + 2] : 0;
            int m3 = (e0 + 3 < s1) ? mask[e0 + 3] : 0;
            int cnt = m0 + m1 + m2 + m3;
            int inc = cnt;
            #pragma unroll
            for (int off = 1; off < 32; off <<= 1) {
                int y = __shfl_up_sync(0xffffffffu, inc, off);
                if (lane >= off) inc += y;
            }
            if (lane == 31) wsum[wid] = inc;
            __syncthreads();
            if (wid == 0) {
                int v = wsum[lane];
                int iv = v;
                #pragma unroll
                for (int off = 1; off < 32; off <<= 1) {
                    int y = __shfl_up_sync(0xffffffffu, iv, off);
                    if (lane >= off) iv += y;
                }
                wsum[lane] = iv - v;
                if (lane == 31) s_tot = iv;
            }
            __syncthreads();
            int pos = s_run + wsum[wid] + (inc - cnt);
            if (m0) { if (pos < stride) ob[pos] = (float)(e0 + 0); pos++; }
            if (m1) { if (pos < stride) ob[pos] = (float)(e0 + 1); pos++; }
            if (m2) { if (pos < stride) ob[pos] = (float)(e0 + 2); pos++; }
            if (m3) { if (pos < stride) ob[pos] = (float)(e0 + 3); pos++; }
            __syncthreads();
            if (tid == 0) s_run += s_tot;
            __syncthreads();
        }
    }

    // tail fill (padding region, if any)
    if (blockIdx.x == 0) {
        for (int i = NOUT + tid; i < stride; i += 1024) ob[i] = (float)EE;
    }
}

// ---------------- launch ----------------
extern "C" void kernel_launch(void* const* d_in, const int* in_sizes, int n_in,
                              void* d_out, int out_size) {
    const float* fm = (const float*)d_in[0];
    float* out = (float*)d_out;
    (void)in_sizes; (void)n_in;

    int stride = (out_size % BB == 0) ? (out_size / BB) : NOUT;

    const int T = 256;
    init_kernel<<<(BB*EE + T - 1) / T, T>>>();
    weight_kernel<<<(BB*VV + T - 1) / T, T>>>(fm);

    dim3 pgrid(NBLK, BB);
    boruvka_kernel<<<pgrid, 1024>>>(out, stride);
}

// round 8
// speedup vs baseline: 3.4369x; 1.0149x over previous
#include <cuda_runtime.h>

// ---------------- problem constants (fixed shapes) ----------------
#define BB   4
#define CC   64
#define HH   288
#define WW   432
#define PW   72            // W / TEM
#define TEM_ 6
#define VV   (HH*WW)       // 124416
#define RN   ((HH-1)*PW)   // 20664  vertical edges per phase
#define CN   (HH*(PW-1))   // 20448  horizontal edges per phase
#define XN   (HH*PW)       // 20736  cross edges per phase pair
#define PB   (RN+CN)       // 41112  weight-layout per-phase block
#define EE   (6*RN+6*CN+5*XN) // 350352 total edges
#define NOUT (VV-1)        // 124415 output entries per batch
#define SENT 0xFFFFFFFFFFFFFFFFULL
#define NROUNDS 18

#define NBLK 32                    // blocks per batch (128 total <= 148 SMs -> co-resident)
#define TPB  (NBLK*1024)           // threads per batch
#define SEG  ((EE + NBLK - 1) / NBLK)  // compaction segment per block

#define NGRP (VV/4)                // 4-pixel groups per batch (31104)

typedef unsigned long long u64;

// ---------------- scratch (device globals; no allocation) ----------------
__device__ u64 g_keys[BB*EE];          // (w_bits<<32)|e at weight-layout position e
__device__ u64 g_minkey[BB*VV];        // per-component min key (rounds >= 1)
__device__ u64 g_euv[BB*EE];           // current (cu,cv) of surviving edge e
__device__ int g_comp[BB*VV];
__device__ int g_parent[BB*VV];
__device__ unsigned char g_mask[BB*EE];
__device__ ulonglong2 g_elist[2][BB*EE];  // {key, (cv<<32)|cu}
__device__ int g_ecnt[NROUNDS][BB];
__device__ int g_rcnt[NROUNDS][BB];
__device__ int g_roots[2][BB*VV];
__device__ unsigned g_barcnt[BB];
__device__ int g_bcnt[BB*NBLK];

// endpoints of edge e in INDEX layout: [rows x6 | cols x6 | cross x5]
__device__ __forceinline__ void edge_uv(int e, int& u, int& v) {
    if (e < 6*RN) {
        int i = e / RN; int j = e - i*RN;
        int r = j / PW;  int c = j - r*PW;
        u = r*WW + i*PW + c; v = u + WW;
    } else if (e < 6*RN + 6*CN) {
        int t = e - 6*RN;
        int i = t / CN; int j = t - i*CN;
        int r = j / (PW-1); int c = j - r*(PW-1);
        u = r*WW + i*PW + c; v = u + 1;
    } else {
        int t = e - 6*RN - 6*CN;
        int i = t / XN; int j = t - i*XN;
        int r = j / PW; int c = j - r*PW;
        u = r*WW + i*PW + c; v = u + PW;
    }
}

__device__ __forceinline__ int chase_root(const int* par, int c) {
    for (int it = 0; it < VV + 2; it++) {
        int p = par[c];
        if (p == c) break;
        int gp = par[p];
        if (gp == c) { c = (c < p) ? c : p; break; }  // 2-cycle: min of pair
        c = p;
    }
    return c;
}

// per-batch grid barrier (all NBLK blocks of batch b co-resident by construction)
__device__ __forceinline__ void batch_barrier(int b, unsigned& target) {
    __syncthreads();
    if (threadIdx.x == 0) {
        __threadfence();
        atomicAdd(&g_barcnt[b], 1u);
        target += NBLK;
        volatile unsigned* p = &g_barcnt[b];
        while (*p < target) { __nanosleep(64); }
        __threadfence();
    }
    __syncthreads();
}

// warp-aggregated list append; must be called by all 32 lanes
__device__ __forceinline__ int warp_reserve(int* ctr, bool pred) {
    unsigned ball = __ballot_sync(0xffffffffu, pred);
    int lane = threadIdx.x & 31;
    int total = __popc(ball);
    int base = 0;
    if (lane == 0 && total) base = atomicAdd(ctr, total);
    base = __shfl_sync(0xffffffffu, base, 0);
    return base + __popc(ball & ((1u << lane) - 1u));
}

__device__ __forceinline__ u64 pack_key(float w, int e) {
    return ((u64)__float_as_uint(w) << 32) | (unsigned)e;
}

// ---------------- weights (4 px / thread, float4) + scratch init ----------------
__global__ void __launch_bounds__(256) weight_kernel(const float* __restrict__ fm) {
    int idx = blockIdx.x * blockDim.x + threadIdx.x;
    if (idx >= BB*NGRP) return;
    int b   = idx / NGRP;
    int g   = idx - b*NGRP;
    int pix = g * 4;
    int r   = pix / WW;
    int col = pix - r*WW;
    int ph  = col / PW;
    int c   = col - ph*PW;            // multiple of 4, <= 68; group never spans phase/row

    bool hasV  = (r  < HH-1);
    bool hasX  = (ph < TEM_-1);
    bool hasH3 = (c  < PW-4);         // element 3's H edge exists iff c+3 < PW-1

    const float* p0 = fm + (size_t)b * CC * VV + pix;
    float sv0=0,sv1=0,sv2=0,sv3=0, sh0=0,sh1=0,sh2=0,sh3=0, sx0=0,sx1=0,sx2=0,sx3=0;

    #pragma unroll 4
    for (int ch = 0; ch < CC; ch++) {
        const float* p = p0 + (size_t)ch * VV;
        float4 x = *reinterpret_cast<const float4*>(p);
        float x4 = hasH3 ? __ldg(p + 4) : 0.f;
        if (hasV) {
            float4 d = *reinterpret_cast<const float4*>(p + WW);
            float t0 = x.x - d.x, t1 = x.y - d.y, t2 = x.z - d.z, t3 = x.w - d.w;
            sv0 += t0*t0; sv1 += t1*t1; sv2 += t2*t2; sv3 += t3*t3;
        }
        {
            float t0 = x.x - x.y, t1 = x.y - x.z, t2 = x.z - x.w, t3 = x.w - x4;
            sh0 += t0*t0; sh1 += t1*t1; sh2 += t2*t2; sh3 += t3*t3;
        }
        if (hasX) {
            float4 d = *reinterpret_cast<const float4*>(p + PW);
            float t0 = x.x - d.x, t1 = x.y - d.y, t2 = x.z - d.z, t3 = x.w - d.w;
            sx0 += t0*t0; sx1 += t1*t1; sx2 += t2*t2; sx3 += t3*t3;
        }
    }

    u64* kb = g_keys + (size_t)b * EE;
    if (hasV) {
        int e = ph*PB + r*PW + c;
        kb[e+0] = pack_key(sv0, e+0); kb[e+1] = pack_key(sv1, e+1);
        kb[e+2] = pack_key(sv2, e+2); kb[e+3] = pack_key(sv3, e+3);
    }
    {
        int e = ph*PB + RN + r*(PW-1) + c;
        kb[e+0] = pack_key(sh0, e+0); kb[e+1] = pack_key(sh1, e+1);
        kb[e+2] = pack_key(sh2, e+2);
        if (hasH3) kb[e+3] = pack_key(sh3, e+3);
    }
    if (hasX) {
        int e = 6*PB + ph*XN + r*PW + c;
        kb[e+0] = pack_key(sx0, e+0); kb[e+1] = pack_key(sx1, e+1);
        kb[e+2] = pack_key(sx2, e+2); kb[e+3] = pack_key(sx3, e+3);
    }

    // ---- fused scratch init (idx in [0, BB*NGRP) = [0, 124416)) ----
    {   // minkey: 4 u64 per thread, exactly BB*VV
        ulonglong2 s2 = make_ulonglong2(SENT, SENT);
        ulonglong2* mk = reinterpret_cast<ulonglong2*>(g_minkey) + idx*2;
        mk[0] = s2; mk[1] = s2;
    }
    {   // mask zero: BB*EE bytes = 175176 u64
        u64* m8 = reinterpret_cast<u64*>(g_mask);
        for (int i = idx; i < (BB*EE)/8; i += BB*NGRP) m8[i] = 0ULL;
    }
    if (idx < NROUNDS*BB) { (&g_ecnt[0][0])[idx] = 0; (&g_rcnt[0][0])[idx] = 0; }
    if (idx < BB)         g_barcnt[idx] = 0;
    if (idx < BB*NBLK)    g_bcnt[idx] = 0;
}

// ---------------- persistent Boruvka + compaction ----------------
__global__ void __launch_bounds__(1024, 1) boruvka_kernel(float* __restrict__ out, int stride) {
    int b   = blockIdx.y;
    int tid = threadIdx.x;
    int gt  = blockIdx.x * 1024 + tid;
    unsigned bar_target = 0;

    u64* minkey = g_minkey + b*VV;
    u64* keys   = g_keys + (size_t)b*EE;
    u64* euv    = g_euv  + (size_t)b*EE;
    int* parent = g_parent + b*VV;
    int* comp   = g_comp + b*VV;
    unsigned char* mask = g_mask + (size_t)b*EE;

    // ===== round 0: per-vertex gather over <=6 incident edges (INDEX layout ids) =====
    for (int x = gt; x < VV; x += TPB) {
        int r = x / WW; int col = x - r*WW; int ph = col / PW; int c = col - ph*PW;
        u64 best = SENT;
        u64 k;
        // vertical edges (index region [0, 6*RN), block ph)
        int ev = ph*RN + r*PW + c;
        if (r < HH-1) { k = keys[ev];        if (k < best) best = k; }
        if (r > 0)    { k = keys[ev - PW];   if (k < best) best = k; }
        // horizontal edges (index region [6*RN, 6*RN+6*CN), block ph)
        int eh = 6*RN + ph*CN + r*(PW-1) + c;
        if (c < PW-1) { k = keys[eh];        if (k < best) best = k; }
        if (c > 0)    { k = keys[eh - 1];    if (k < best) best = k; }
        // cross edges (index region [6*RN+6*CN, EE), block ph)
        int ex = 6*RN + 6*CN + ph*XN + r*PW + c;
        if (ph < TEM_-1) { k = keys[ex];      if (k < best) best = k; }
        if (ph > 0)      { k = keys[ex - XN]; if (k < best) best = k; }

        int e = (int)(unsigned)(best & 0xFFFFFFFFu);
        mask[e] = 1;
        int u, v; edge_uv(e, u, v);
        parent[x] = (u == x) ? v : u;
    }
    batch_barrier(b, bar_target);

    // round 0: chase over all V, collect roots -> roots[0]
    {
        const int nn = ((VV + TPB - 1) / TPB) * TPB;
        for (int x = gt; x < nn; x += TPB) {
            bool isroot = false;
            if (x < VV) {
                int c = chase_root(parent, x);
                comp[x] = c;
                isroot = (c == x);
            }
            int pos = warp_reserve(&g_rcnt[0][b], isroot);
            if (isroot) g_roots[0][b*VV + pos] = x;
        }
    }
    batch_barrier(b, bar_target);

    // ===== rounds 1..17 =====
    for (int r = 1; r < NROUNDS; r++) {
        int ebuf = r & 1;          // write buffer this round
        int rb   = (r - 1) & 1;    // root read buffer
        int wb   = r & 1;          // root write buffer

        // edge phase
        if (r == 1) {
            const int nn = ((EE + TPB - 1) / TPB) * TPB;
            for (int i = gt; i < nn; i += TPB) {
                bool pred = false; u64 k = 0, uvp = 0;
                if (i < EE) {
                    int u, v; edge_uv(i, u, v);
                    int cu = comp[u], cv = comp[v];
                    if (cu != cv) {
                        pred = true;
                        k = keys[i];
                        atomicMin(&minkey[cu], k);
                        atomicMin(&minkey[cv], k);
                        uvp = ((u64)(unsigned)cv << 32) | (unsigned)cu;
                        euv[i] = uvp;
                    }
                }
                int pos = warp_reserve(&g_ecnt[1][b], pred);
                if (pred) g_elist[ebuf][(size_t)b*EE + pos] = make_ulonglong2(k, uvp);
            }
        } else {
            int n = g_ecnt[r-1][b];
            const ulonglong2* src = g_elist[ebuf ^ 1] + (size_t)b*EE;
            ulonglong2* dst = g_elist[ebuf] + (size_t)b*EE;
            int nn = ((n + TPB - 1) / TPB) * TPB;
            for (int i = gt; i < nn; i += TPB) {
                bool pred = false; u64 k = 0, uvp = 0;
                if (i < n) {
                    ulonglong2 ed = src[i];
                    int u = (int)(unsigned)(ed.y & 0xFFFFFFFFu);
                    int v = (int)(unsigned)(ed.y >> 32);
                    int cu = comp[u], cv = comp[v];
                    if (cu != cv) {
                        pred = true;
                        k = ed.x;
                        atomicMin(&minkey[cu], k);
                        atomicMin(&minkey[cv], k);
                        uvp = ((u64)(unsigned)cv << 32) | (unsigned)cu;
                        euv[(unsigned)(k & 0xFFFFFFFFu)] = uvp;
                    }
                }
                int pos = warp_reserve(&g_ecnt[r][b], pred);
                if (pred) dst[pos] = make_ulonglong2(k, uvp);
            }
        }
        batch_barrier(b, bar_target);

        if (g_ecnt[r][b] == 0) break;   // fully merged -> done

        // select phase over root list
        {
            int n = g_rcnt[r-1][b];
            const int* rl = g_roots[rb] + b*VV;
            for (int i = gt; i < n; i += TPB) {
                int c = rl[i];
                u64 mk = minkey[c];
                int par = c;
                if (mk != SENT) {
                    minkey[c] = SENT;
                    int e = (int)(unsigned)(mk & 0xFFFFFFFFu);
                    mask[e] = 1;
                    u64 uvp = euv[e];
                    int cu = (int)(unsigned)(uvp & 0xFFFFFFFFu);
                    int cv = (int)(unsigned)(uvp >> 32);
                    par = (cu == c) ? cv : cu;
                }
                parent[c] = par;
            }
        }
        batch_barrier(b, bar_target);

        // chase phase over root list, collect surviving roots
        {
            int n = g_rcnt[r-1][b];
            const int* rl = g_roots[rb] + b*VV;
            int nn = ((n + TPB - 1) / TPB) * TPB;
            for (int i = gt; i < nn; i += TPB) {
                bool isroot = false;
                int x = 0;
                if (i < n) {
                    x = rl[i];
                    int c = chase_root(parent, x);
                    comp[x] = c;
                    isroot = (c == x);
                }
                int pos = warp_reserve(&g_rcnt[r][b], isroot);
                if (isroot) g_roots[wb][b*VV + pos] = x;
            }
        }
        batch_barrier(b, bar_target);
    }

    // ===== fused compaction: mask -> ascending edge indices (float out) =====
    float* ob = out + (size_t)b * stride;

    // pass 1: count this block's segment
    {
        int s0 = blockIdx.x * SEG;
        int s1 = min(EE, s0 + SEG);
        int cnt = 0;
        for (int i = s0 + tid; i < s1; i += 1024) cnt += mask[i];
        __shared__ int s_red[32];
        int lane = tid & 31, wid = tid >> 5;
        #pragma unroll
        for (int off = 16; off > 0; off >>= 1) cnt += __shfl_down_sync(0xffffffffu, cnt, off);
        if (lane == 0) s_red[wid] = cnt;
        __syncthreads();
        if (wid == 0) {
            int v = s_red[lane];
            #pragma unroll
            for (int off = 16; off > 0; off >>= 1) v += __shfl_down_sync(0xffffffffu, v, off);
            if (lane == 0) g_bcnt[b*NBLK + blockIdx.x] = v;
        }
    }
    batch_barrier(b, bar_target);

    // block base = exclusive sum over preceding blocks
    __shared__ int s_base;
    if (tid < 32) {
        int v = g_bcnt[b*NBLK + tid];
        int iv = v;
        #pragma unroll
        for (int off = 1; off < 32; off <<= 1) {
            int y = __shfl_up_sync(0xffffffffu, iv, off);
            if (tid >= off) iv += y;
        }
        if (tid == (int)blockIdx.x) s_base = iv - v;
    }
    __syncthreads();

    // pass 2: ordered scatter within segment
    {
        int s0 = blockIdx.x * SEG;
        int s1 = min(EE, s0 + SEG);
        __shared__ int wsum[32];
        __shared__ int s_run, s_tot;
        if (tid == 0) s_run = s_base;
        __syncthreads();
        int lane = tid & 31, wid = tid >> 5;
        for (int chunk = s0; chunk < s1; chunk += 4096) {
            int e0 = chunk + tid*4;
            int m0 = (e0 + 0 < s1) ? mask[e0 + 0] : 0;
            int m1 = (e0 + 1 < s1) ? mask[e0 + 1] : 0;
            int m2 = (e0 + 2 < s1) ? mask[e0 + 2] : 0;
            int m3 = (e0 + 3 < s1) ? mask[e0 + 3] : 0;
            int cnt = m0 + m1 + m2 + m3;
            int inc = cnt;
            #pragma unroll
            for (int off = 1; off < 32; off <<= 1) {
                int y = __shfl_up_sync(0xffffffffu, inc, off);
                if (lane >= off) inc += y;
            }
            if (lane == 31) wsum[wid] = inc;
            __syncthreads();
            if (wid == 0) {
                int v = wsum[lane];
                int iv = v;
                #pragma unroll
                for (int off = 1; off < 32; off <<= 1) {
                    int y = __shfl_up_sync(0xffffffffu, iv, off);
                    if (lane >= off) iv += y;
                }
                wsum[lane] = iv - v;
                if (lane == 31) s_tot = iv;
            }
            __syncthreads();
            int pos = s_run + wsum[wid] + (inc - cnt);
            if (m0) { if (pos < stride) ob[pos] = (float)(e0 + 0); pos++; }
            if (m1) { if (pos < stride) ob[pos] = (float)(e0 + 1); pos++; }
            if (m2) { if (pos < stride) ob[pos] = (float)(e0 + 2); pos++; }
            if (m3) { if (pos < stride) ob[pos] = (float)(e0 + 3); pos++; }
            __syncthreads();
            if (tid == 0) s_run += s_tot;
            __syncthreads();
        }
    }

    // tail fill (padding region, if any)
    if (blockIdx.x == 0) {
        for (int i = NOUT + tid; i < stride; i += 1024) ob[i] = (float)EE;
    }
}

// ---------------- launch ----------------
extern "C" void kernel_launch(void* const* d_in, const int* in_sizes, int n_in,
                              void* d_out, int out_size) {
    const float* fm = (const float*)d_in[0];
    float* out = (float*)d_out;
    (void)in_sizes; (void)n_in;

    int stride = (out_size % BB == 0) ? (out_size / BB) : NOUT;

    weight_kernel<<<(BB*NGRP + 255) / 256, 256>>>(fm);

    dim3 pgrid(NBLK, BB);
    boruvka_kernel<<<pgrid, 1024>>>(out, stride);
}